// round 3
// baseline (speedup 1.0000x reference)
#include <cuda_runtime.h>
#include <cuda_bf16.h>
#include <cstdint>
#include <cstddef>

// ---------------- problem constants ----------------
#define NB      65536
#define NTILE   512            // NB / 128
#define THREADS 256

#define KP1 136                // padded k-stride (elems) for k=128 tiles
#define KPX 264                // padded k-stride for k=256 X tile
#define KPW 136

// smem sizes (bytes)
#define SMEM_L1 (1024 + 2*128*KP1*2 + 2*256*KP1*2)   // 209920
#define SMEM_L2 (2048 + 2*128*KPX*2 + 2*128*KPW*2)   // 206848

// ---------------- device scratch (no runtime allocation allowed) ----------------
__device__ uint32_t g_x1p[(size_t)NB * 256];  // layer1 activations, packed bf16 hi|lo
__device__ float    g_part[2 * NB];           // per-N-half head partials
__device__ float    g_wc[256];                // combined head weight
__device__ float    g_bc;                     // combined head bias

// ---------------- helpers ----------------
__device__ __forceinline__ void split_bf16(float v, uint16_t& hb, uint16_t& lb) {
    __nv_bfloat16 h = __float2bfloat16(v);
    __nv_bfloat16 l = __float2bfloat16(v - __bfloat162float(h));
    hb = *reinterpret_cast<uint16_t*>(&h);
    lb = *reinterpret_cast<uint16_t*>(&l);
}
__device__ __forceinline__ uint32_t pack_split(float v) {
    uint16_t hb, lb; split_bf16(v, hb, lb);
    return (uint32_t)hb | ((uint32_t)lb << 16);
}

// mma.sync m16n8k16 bf16 (sm_80+ baseline PTX -> HMMA, valid on sm_103 target)
__device__ __forceinline__ void mma_bf16(float* c, const uint32_t* a, const uint32_t* b) {
    asm volatile(
        "mma.sync.aligned.m16n8k16.row.col.f32.bf16.bf16.f32 "
        "{%0,%1,%2,%3},{%4,%5,%6,%7},{%8,%9},{%0,%1,%2,%3};"
        : "+f"(c[0]), "+f"(c[1]), "+f"(c[2]), "+f"(c[3])
        : "r"(a[0]), "r"(a[1]), "r"(a[2]), "r"(a[3]), "r"(b[0]), "r"(b[1]));
}

// ---------------- prep: collapse 200 heads ----------------
__global__ void k_prep(const float* __restrict__ alphas, const float* __restrict__ Wh,
                       const float* __restrict__ bh) {
    int k = threadIdx.x;   // 256 threads
    float s = 0.0f;
    for (int h = 0; h < 200; h++) s += alphas[h] * Wh[h * 256 + k];
    g_wc[k] = s;
    if (k == 0) {
        float b = 0.0f;
        for (int h = 0; h < 200; h++) b += alphas[h] * bh[h];
        g_bc = b;
    }
}

// ---------------- layer 1: x1 = relu([state|action] @ W1^T + b1), packed bf16x2 out ----------------
__global__ __launch_bounds__(THREADS, 1)
void k_l1(const float* __restrict__ state, const float* __restrict__ action,
          const float* __restrict__ W1, const float* __restrict__ b1)
{
    extern __shared__ char smem[];
    float*    b1s = (float*)smem;                          // [256]
    uint16_t* Ah  = (uint16_t*)(smem + 1024);              // [128][KP1]
    uint16_t* Al  = Ah + 128 * KP1;
    uint16_t* Ws  = Al + 128 * KP1;                        // hi [256][KP1]
    uint16_t* Wl  = Ws + 256 * KP1;

    const int tid = threadIdx.x;
    const int row0 = blockIdx.x * 128;

    b1s[tid] = b1[tid];

    // W1 [256 out x 128 k] -> hi/lo bf16
    for (int idx = tid; idx < 256 * 128; idx += THREADS) {
        int n = idx >> 7, k = idx & 127;
        uint16_t hb, lb; split_bf16(W1[idx], hb, lb);
        Ws[n * KP1 + k] = hb;  Wl[n * KP1 + k] = lb;
    }
    // X tile [128 x 128] = concat(state, action) -> hi/lo bf16
    for (int idx = tid; idx < 128 * 128; idx += THREADS) {
        int r = idx >> 7, k = idx & 127;
        float v = (k < 96) ? state[(size_t)(row0 + r) * 96 + k]
                           : action[(size_t)(row0 + r) * 32 + (k - 96)];
        uint16_t hb, lb; split_bf16(v, hb, lb);
        Ah[r * KP1 + k] = hb;  Al[r * KP1 + k] = lb;
    }
    __syncthreads();

    const int wid = tid >> 5, lane = tid & 31, g = lane >> 2, tg = lane & 3;
    const int wm = (wid & 1) * 64, wn = (wid >> 1) * 64;

    float acc[4][8][4];
    #pragma unroll
    for (int i = 0; i < 4; i++)
        #pragma unroll
        for (int j = 0; j < 8; j++)
            #pragma unroll
            for (int c = 0; c < 4; c++) acc[i][j][c] = 0.0f;

    #pragma unroll
    for (int pass = 0; pass < 3; pass++) {
        const uint16_t* As = (pass == 2) ? Al : Ah;
        const uint16_t* Bs = (pass == 1) ? Wl : Ws;
        #pragma unroll
        for (int ks = 0; ks < 8; ks++) {
            const int kk = ks * 16 + tg * 2;
            uint32_t a[4][4];
            #pragma unroll
            for (int mi = 0; mi < 4; mi++) {
                int r = wm + mi * 16 + g;
                a[mi][0] = *(const uint32_t*)&As[r * KP1 + kk];
                a[mi][1] = *(const uint32_t*)&As[(r + 8) * KP1 + kk];
                a[mi][2] = *(const uint32_t*)&As[r * KP1 + kk + 8];
                a[mi][3] = *(const uint32_t*)&As[(r + 8) * KP1 + kk + 8];
            }
            uint32_t b[8][2];
            #pragma unroll
            for (int nj = 0; nj < 8; nj++) {
                int n = wn + nj * 8 + g;
                b[nj][0] = *(const uint32_t*)&Bs[n * KP1 + kk];
                b[nj][1] = *(const uint32_t*)&Bs[n * KP1 + kk + 8];
            }
            #pragma unroll
            for (int mi = 0; mi < 4; mi++)
                #pragma unroll
                for (int nj = 0; nj < 8; nj++)
                    mma_bf16(acc[mi][nj], a[mi], b[nj]);
        }
    }

    // epilogue: bias + relu, split to bf16 hi/lo, packed u32 stores (8B per pair)
    #pragma unroll
    for (int mi = 0; mi < 4; mi++) {
        #pragma unroll
        for (int nj = 0; nj < 8; nj++) {
            int rA = row0 + wm + mi * 16 + g;
            int c0 = wn + nj * 8 + tg * 2;
            uint2 p0, p1;
            p0.x = pack_split(fmaxf(acc[mi][nj][0] + b1s[c0],     0.0f));
            p0.y = pack_split(fmaxf(acc[mi][nj][1] + b1s[c0 + 1], 0.0f));
            p1.x = pack_split(fmaxf(acc[mi][nj][2] + b1s[c0],     0.0f));
            p1.y = pack_split(fmaxf(acc[mi][nj][3] + b1s[c0 + 1], 0.0f));
            *(uint2*)&g_x1p[(size_t)rA * 256 + c0]       = p0;
            *(uint2*)&g_x1p[(size_t)(rA + 8) * 256 + c0] = p1;
        }
    }
}

// ---------------- layer 2 + head: g_part[half][row] = sum_n relu(x1@W2h^T + b2h)[n] * wc[n] ----------------
__global__ __launch_bounds__(THREADS, 1)
void k_l2(const float* __restrict__ W2, const float* __restrict__ b2)
{
    extern __shared__ char smem[];
    float*    b2s   = (float*)smem;           // [128]
    float*    wcs   = b2s + 128;              // [128]
    float*    stage = wcs + 128;              // [128]
    uint16_t* Xh    = (uint16_t*)(smem + 2048);  // [128][KPX]
    uint16_t* Xl    = Xh + 128 * KPX;
    uint16_t* Wsh   = Xl + 128 * KPX;            // [128][KPW] (k-chunk)
    uint16_t* Wsl   = Wsh + 128 * KPW;

    const int tid  = threadIdx.x;
    const int t    = blockIdx.x >> 1;
    const int half = blockIdx.x & 1;
    const int row0 = t * 128;

    if (tid < 128) {
        b2s[tid]   = b2[half * 128 + tid];
        wcs[tid]   = g_wc[half * 128 + tid];
        stage[tid] = 0.0f;
    }
    // X tile [128 x 256], unpack packed bf16 pair
    for (int idx = tid; idx < 128 * 256; idx += THREADS) {
        int r = idx >> 8, k = idx & 255;
        uint32_t p = g_x1p[(size_t)(row0 + r) * 256 + k];
        Xh[r * KPX + k] = (uint16_t)(p & 0xFFFFu);
        Xl[r * KPX + k] = (uint16_t)(p >> 16);
    }

    const int wid = tid >> 5, lane = tid & 31, g = lane >> 2, tg = lane & 3;
    const int wm = (wid & 1) * 64, wn = (wid >> 1) * 32;

    float acc[4][4][4];
    #pragma unroll
    for (int i = 0; i < 4; i++)
        #pragma unroll
        for (int j = 0; j < 4; j++)
            #pragma unroll
            for (int c = 0; c < 4; c++) acc[i][j][c] = 0.0f;

    for (int kc = 0; kc < 2; kc++) {
        if (kc) __syncthreads();   // all warps done reading previous W chunk
        // W2 half, k-chunk [128 n x 128 k] -> hi/lo
        for (int idx = tid; idx < 128 * 128; idx += THREADS) {
            int n = idx >> 7, k = idx & 127;
            float w = W2[(size_t)(half * 128 + n) * 256 + kc * 128 + k];
            uint16_t hb, lb; split_bf16(w, hb, lb);
            Wsh[n * KPW + k] = hb;  Wsl[n * KPW + k] = lb;
        }
        __syncthreads();

        #pragma unroll
        for (int pass = 0; pass < 3; pass++) {
            const uint16_t* As = (pass == 2) ? Xl : Xh;
            const uint16_t* Bs = (pass == 1) ? Wsl : Wsh;
            #pragma unroll
            for (int ks = 0; ks < 8; ks++) {
                const int kx = kc * 128 + ks * 16 + tg * 2;   // in X (k=256)
                const int kw = ks * 16 + tg * 2;              // in W chunk (k=128)
                uint32_t a[4][4];
                #pragma unroll
                for (int mi = 0; mi < 4; mi++) {
                    int r = wm + mi * 16 + g;
                    a[mi][0] = *(const uint32_t*)&As[r * KPX + kx];
                    a[mi][1] = *(const uint32_t*)&As[(r + 8) * KPX + kx];
                    a[mi][2] = *(const uint32_t*)&As[r * KPX + kx + 8];
                    a[mi][3] = *(const uint32_t*)&As[(r + 8) * KPX + kx + 8];
                }
                uint32_t b[4][2];
                #pragma unroll
                for (int nj = 0; nj < 4; nj++) {
                    int n = wn + nj * 8 + g;
                    b[nj][0] = *(const uint32_t*)&Bs[n * KPW + kw];
                    b[nj][1] = *(const uint32_t*)&Bs[n * KPW + kw + 8];
                }
                #pragma unroll
                for (int mi = 0; mi < 4; mi++)
                    #pragma unroll
                    for (int nj = 0; nj < 4; nj++)
                        mma_bf16(acc[mi][nj], a[mi], b[nj]);
            }
        }
    }

    // fused epilogue: bias + relu + head dot, reduce to per-row scalar
    float rs[4][2];
    #pragma unroll
    for (int mi = 0; mi < 4; mi++) { rs[mi][0] = 0.0f; rs[mi][1] = 0.0f; }
    #pragma unroll
    for (int mi = 0; mi < 4; mi++) {
        #pragma unroll
        for (int nj = 0; nj < 4; nj++) {
            int c0 = wn + nj * 8 + tg * 2;
            float w0 = wcs[c0], w1 = wcs[c0 + 1];
            float bb0 = b2s[c0], bb1 = b2s[c0 + 1];
            rs[mi][0] += fmaxf(acc[mi][nj][0] + bb0, 0.0f) * w0
                       + fmaxf(acc[mi][nj][1] + bb1, 0.0f) * w1;
            rs[mi][1] += fmaxf(acc[mi][nj][2] + bb0, 0.0f) * w0
                       + fmaxf(acc[mi][nj][3] + bb1, 0.0f) * w1;
        }
    }
    __syncthreads();   // stage[] zeroed and X reads finished before atomics
    #pragma unroll
    for (int mi = 0; mi < 4; mi++) {
        #pragma unroll
        for (int rb = 0; rb < 2; rb++) {
            float s = rs[mi][rb];
            s += __shfl_xor_sync(0xFFFFFFFFu, s, 1);
            s += __shfl_xor_sync(0xFFFFFFFFu, s, 2);
            if (tg == 0) atomicAdd(&stage[wm + mi * 16 + g + rb * 8], s);
        }
    }
    __syncthreads();
    if (tid < 128) g_part[(size_t)half * NB + row0 + tid] = stage[tid];
}

// ---------------- finalize ----------------
__global__ void k_final(float* __restrict__ out) {
    int i = blockIdx.x * blockDim.x + threadIdx.x;
    out[i] = g_part[i] + g_part[NB + i] + g_bc;
}

// ---------------- launch ----------------
extern "C" void kernel_launch(void* const* d_in, const int* in_sizes, int n_in,
                              void* d_out, int out_size) {
    const float* state  = (const float*)d_in[0];
    const float* action = (const float*)d_in[1];
    const float* alphas = (const float*)d_in[2];
    const float* W1     = (const float*)d_in[3];
    const float* b1     = (const float*)d_in[4];
    const float* W2     = (const float*)d_in[5];
    const float* b2     = (const float*)d_in[6];
    const float* Wh     = (const float*)d_in[7];
    const float* bh     = (const float*)d_in[8];
    float* out = (float*)d_out;

    static bool attr_set = false;
    cudaFuncSetAttribute(k_l1, cudaFuncAttributeMaxDynamicSharedMemorySize, SMEM_L1);
    cudaFuncSetAttribute(k_l2, cudaFuncAttributeMaxDynamicSharedMemorySize, SMEM_L2);
    (void)attr_set;

    k_prep<<<1, 256>>>(alphas, Wh, bh);
    k_l1<<<NTILE, THREADS, SMEM_L1>>>(state, action, W1, b1);
    k_l2<<<NTILE * 2, THREADS, SMEM_L2>>>(W2, b2);
    k_final<<<NB / THREADS, THREADS>>>(out);
}

// round 5
// speedup vs baseline: 2.0148x; 2.0148x over previous
#include <cuda_runtime.h>
#include <cuda_bf16.h>
#include <cstdint>
#include <cstddef>

// ---------------- problem constants ----------------
#define NB      65536
#define THREADS 256

// padded k-strides (bf16 elems); row step = 272B/528B -> 4-bank rotation, LDSM conflict-free
#define KP1 136
#define KPX 264
#define KPW 136

// ---------------- smem layouts ----------------
#define L1_BUF  (128 * KP1 * 2)              // 34816 B
#define SM1_XH  1024
#define SM1_XL  (SM1_XH + L1_BUF)
#define SM1_WH  (SM1_XL + L1_BUF)
#define SM1_WL  (SM1_WH + L1_BUF)
#define SMEM_L1 (SM1_WL + L1_BUF)            // 140288 B

#define L2_XBUF (128 * KPX * 2)              // 67584 B
#define L2_WBUF (128 * KPW * 2)              // 34816 B
#define SM2_XH  2048
#define SM2_XL  (SM2_XH + L2_XBUF)
#define SM2_WH  (SM2_XL + L2_XBUF)
#define SM2_WL  (SM2_WH + L2_WBUF)
#define SMEM_L2 (SM2_WL + L2_WBUF)           // 206848 B

// ---------------- device scratch (static; no runtime allocation) ----------------
__device__ __align__(16) uint32_t g_xh32[(size_t)NB * 64];    // X hi plane  [B][128] bf16 as u32 pairs
__device__ __align__(16) uint32_t g_xl32[(size_t)NB * 64];    // X lo plane
__device__ __align__(16) uint32_t g_x1h32[(size_t)NB * 128];  // x1 hi plane [B][256] bf16
__device__ __align__(16) uint32_t g_x1l32[(size_t)NB * 128];  // x1 lo plane
__device__ __align__(16) uint32_t g_w1h32[256 * 64];          // W1 hi [256][128] bf16
__device__ __align__(16) uint32_t g_w1l32[256 * 64];
__device__ __align__(16) uint32_t g_w2h32[256 * 128];         // W2 hi [256][256] bf16
__device__ __align__(16) uint32_t g_w2l32[256 * 128];
__device__ float g_part[2 * NB];
__device__ float g_wc[256];
__device__ float g_bc;

// ---------------- PTX helpers ----------------
__device__ __forceinline__ uint32_t smem_u32(const void* p) {
    uint32_t a;
    asm("{ .reg .u64 t; cvta.to.shared.u64 t, %1; cvt.u32.u64 %0, t; }" : "=r"(a) : "l"(p));
    return a;
}
__device__ __forceinline__ void cp16(uint32_t dst, const void* src) {
    asm volatile("cp.async.cg.shared.global [%0], [%1], 16;" :: "r"(dst), "l"(src));
}
#define CP_COMMIT() asm volatile("cp.async.commit_group;")
#define CP_WAIT0()  asm volatile("cp.async.wait_group 0;" ::: "memory")

__device__ __forceinline__ void ldsm4(uint32_t* r, uint32_t addr) {
    asm volatile("ldmatrix.sync.aligned.m8n8.x4.shared.b16 {%0,%1,%2,%3}, [%4];"
        : "=r"(r[0]), "=r"(r[1]), "=r"(r[2]), "=r"(r[3]) : "r"(addr));
}
__device__ __forceinline__ void mma_bf16(float* c, const uint32_t* a, const uint32_t* b) {
    asm volatile(
        "mma.sync.aligned.m16n8k16.row.col.f32.bf16.bf16.f32 "
        "{%0,%1,%2,%3},{%4,%5,%6,%7},{%8,%9},{%0,%1,%2,%3};"
        : "+f"(c[0]), "+f"(c[1]), "+f"(c[2]), "+f"(c[3])
        : "r"(a[0]), "r"(a[1]), "r"(a[2]), "r"(a[3]), "r"(b[0]), "r"(b[1]));
}

// split two fp32 into packed bf16-hi pair and bf16-lo (residual) pair
__device__ __forceinline__ void split2(float v0, float v1, uint32_t& hi, uint32_t& lo) {
    __nv_bfloat16 h0 = __float2bfloat16(v0), h1 = __float2bfloat16(v1);
    __nv_bfloat16 l0 = __float2bfloat16(v0 - __bfloat162float(h0));
    __nv_bfloat16 l1 = __float2bfloat16(v1 - __bfloat162float(h1));
    hi = (uint32_t)*(uint16_t*)&h0 | ((uint32_t)*(uint16_t*)&h1 << 16);
    lo = (uint32_t)*(uint16_t*)&l0 | ((uint32_t)*(uint16_t*)&l1 << 16);
}

// ---------------- prep: weight splits + head collapse ----------------
__global__ void k_prep(const float* __restrict__ alphas,
                       const float* __restrict__ Wh, const float* __restrict__ bh,
                       const float* __restrict__ W1, const float* __restrict__ W2) {
    int bid = blockIdx.x, tid = threadIdx.x;
    if (bid == 0) {                       // head collapse
        float s = 0.0f;
        for (int h = 0; h < 200; h++) s += alphas[h] * Wh[h * 256 + tid];
        g_wc[tid] = s;
        if (tid == 0) {
            float b = 0.0f;
            for (int h = 0; h < 200; h++) b += alphas[h] * bh[h];
            g_bc = b;
        }
    } else if (bid <= 64) {               // W1 split: 16384 u32 pairs
        int i = (bid - 1) * 256 + tid;
        int row = i >> 6, kp = i & 63;
        split2(W1[row * 128 + kp * 2], W1[row * 128 + kp * 2 + 1], g_w1h32[i], g_w1l32[i]);
    } else {                              // W2 split: 32768 u32 pairs
        int j = (bid - 65) * 256 + tid;
        int row = j >> 7, kp = j & 127;
        split2(W2[row * 256 + kp * 2], W2[row * 256 + kp * 2 + 1], g_w2h32[j], g_w2l32[j]);
    }
}

// ---------------- prep: X = concat(state, action) -> bf16 hi/lo planes ----------------
__global__ void k_prepx(const float* __restrict__ state, const float* __restrict__ action) {
    const size_t total = (size_t)NB * 64;
    for (size_t p = (size_t)blockIdx.x * blockDim.x + threadIdx.x; p < total;
         p += (size_t)gridDim.x * blockDim.x) {
        size_t b = p >> 6;
        int k = (int)(p & 63) * 2;
        float v0, v1;
        if (k < 96) { v0 = state[b * 96 + k];         v1 = state[b * 96 + k + 1]; }
        else        { v0 = action[b * 32 + (k - 96)]; v1 = action[b * 32 + (k - 95)]; }
        split2(v0, v1, g_xh32[p], g_xl32[p]);
    }
}

// ---------------- layer 1: x1 = relu(X @ W1^T + b1) -> hi/lo planes ----------------
__global__ __launch_bounds__(THREADS, 1)
void k_l1(const float* __restrict__ b1)
{
    extern __shared__ char smem[];
    const uint32_t sb = smem_u32(smem);
    const int tid = threadIdx.x;
    const int nh  = blockIdx.x & 1;            // N half (128 cols of 256)
    const int row0 = (blockIdx.x >> 1) * 128;

    float* b1s = (float*)smem;                 // [128]
    if (tid < 128) b1s[tid] = b1[nh * 128 + tid];

    // bulk async loads: X tile (both planes) + W1 half (both planes)
    for (int i = tid; i < 2048; i += THREADS) {
        int r = i >> 4, c = i & 15;            // 16 x 16B chunks per 256B row
        uint32_t dro = (uint32_t)r * (KP1 * 2) + (uint32_t)c * 16;
        cp16(sb + SM1_XH + dro, g_xh32 + (size_t)(row0 + r) * 64 + c * 4);
        cp16(sb + SM1_XL + dro, g_xl32 + (size_t)(row0 + r) * 64 + c * 4);
        cp16(sb + SM1_WH + dro, g_w1h32 + (size_t)(nh * 128 + r) * 64 + c * 4);
        cp16(sb + SM1_WL + dro, g_w1l32 + (size_t)(nh * 128 + r) * 64 + c * 4);
    }
    CP_COMMIT(); CP_WAIT0();
    __syncthreads();

    const int wid = tid >> 5, lane = tid & 31;
    const int wm = (wid & 1) * 64, wn = (wid >> 1) * 32;

    // ldmatrix per-thread address components
    const uint32_t aoff = (((uint32_t)(wm + (lane & 15))) * KP1 + ((lane >> 4) * 8)) * 2;
    const uint32_t boff = (((uint32_t)(wn + (lane & 7) + ((lane >> 4) * 8))) * KP1
                           + (((lane >> 3) & 1) * 8)) * 2;

    float acc[4][4][4];
    #pragma unroll
    for (int i = 0; i < 4; i++)
        #pragma unroll
        for (int j = 0; j < 4; j++)
            #pragma unroll
            for (int c = 0; c < 4; c++) acc[i][j][c] = 0.0f;

    #pragma unroll
    for (int pass = 0; pass < 3; pass++) {
        const uint32_t Ab = sb + ((pass == 2) ? SM1_XL : SM1_XH) + aoff;
        const uint32_t Bb = sb + ((pass == 1) ? SM1_WL : SM1_WH) + boff;
        #pragma unroll
        for (int ks = 0; ks < 8; ks++) {
            uint32_t a[4][4], b[2][4];
            #pragma unroll
            for (int mi = 0; mi < 4; mi++) ldsm4(a[mi], Ab + (mi * 16 * KP1 + ks * 16) * 2);
            #pragma unroll
            for (int nb = 0; nb < 2; nb++) ldsm4(b[nb], Bb + (nb * 16 * KP1 + ks * 16) * 2);
            #pragma unroll
            for (int mi = 0; mi < 4; mi++) {
                mma_bf16(acc[mi][0], a[mi], &b[0][0]);
                mma_bf16(acc[mi][1], a[mi], &b[0][2]);
                mma_bf16(acc[mi][2], a[mi], &b[1][0]);
                mma_bf16(acc[mi][3], a[mi], &b[1][2]);
            }
        }
    }

    // epilogue: bias + relu -> re-split hi/lo, packed u32 pair stores
    const int g = lane >> 2, tg = lane & 3;
    #pragma unroll
    for (int mi = 0; mi < 4; mi++) {
        #pragma unroll
        for (int nj = 0; nj < 4; nj++) {
            int rA = row0 + wm + mi * 16 + g;
            int colL = wn + nj * 8 + tg * 2;
            float v0 = fmaxf(acc[mi][nj][0] + b1s[colL],     0.0f);
            float v1 = fmaxf(acc[mi][nj][1] + b1s[colL + 1], 0.0f);
            float v2 = fmaxf(acc[mi][nj][2] + b1s[colL],     0.0f);
            float v3 = fmaxf(acc[mi][nj][3] + b1s[colL + 1], 0.0f);
            uint32_t h01, l01, h23, l23;
            split2(v0, v1, h01, l01);
            split2(v2, v3, h23, l23);
            size_t ix = (size_t)rA * 128 + nh * 64 + (colL >> 1);
            g_x1h32[ix] = h01;            g_x1l32[ix] = l01;
            g_x1h32[ix + 8 * 128] = h23;  g_x1l32[ix + 8 * 128] = l23;
        }
    }
}

// ---------------- layer 2 + head: g_part[half][row] ----------------
__global__ __launch_bounds__(THREADS, 1)
void k_l2(const float* __restrict__ b2)
{
    extern __shared__ char smem[];
    const uint32_t sb = smem_u32(smem);
    const int tid  = threadIdx.x;
    const int half = blockIdx.x & 1;
    const int row0 = (blockIdx.x >> 1) * 128;

    float* b2s   = (float*)smem;        // [128]
    float* wcs   = b2s + 128;           // [128]
    float* stage = wcs + 128;           // [128]
    if (tid < 128) {
        b2s[tid]   = b2[half * 128 + tid];
        wcs[tid]   = g_wc[half * 128 + tid];
        stage[tid] = 0.0f;
    }

    // X tile [128][256] hi/lo: 32 x 16B chunks per row per plane
    for (int i = tid; i < 4096; i += THREADS) {
        int r = i >> 5, c = i & 31;
        uint32_t dro = (uint32_t)r * (KPX * 2) + (uint32_t)c * 16;
        cp16(sb + SM2_XH + dro, g_x1h32 + (size_t)(row0 + r) * 128 + c * 4);
        cp16(sb + SM2_XL + dro, g_x1l32 + (size_t)(row0 + r) * 128 + c * 4);
    }
    CP_COMMIT();

    const int wid = tid >> 5, lane = tid & 31;
    const int wm = (wid & 1) * 64, wn = (wid >> 1) * 32;

    const uint32_t aoff = (((uint32_t)(wm + (lane & 15))) * KPX + ((lane >> 4) * 8)) * 2;
    const uint32_t boff = (((uint32_t)(wn + (lane & 7) + ((lane >> 4) * 8))) * KPW
                           + (((lane >> 3) & 1) * 8)) * 2;

    float acc[4][4][4];
    #pragma unroll
    for (int i = 0; i < 4; i++)
        #pragma unroll
        for (int j = 0; j < 4; j++)
            #pragma unroll
            for (int c = 0; c < 4; c++) acc[i][j][c] = 0.0f;

    for (int kc = 0; kc < 2; kc++) {
        if (kc) __syncthreads();   // all warps done reading previous W chunk
        // W2-half k-chunk [128n][128k] hi/lo
        for (int i = tid; i < 2048; i += THREADS) {
            int r = i >> 4, c = i & 15;
            uint32_t dro = (uint32_t)r * (KPW * 2) + (uint32_t)c * 16;
            cp16(sb + SM2_WH + dro, g_w2h32 + (size_t)(half * 128 + r) * 128 + kc * 64 + c * 4);
            cp16(sb + SM2_WL + dro, g_w2l32 + (size_t)(half * 128 + r) * 128 + kc * 64 + c * 4);
        }
        CP_COMMIT(); CP_WAIT0();
        __syncthreads();

        #pragma unroll
        for (int pass = 0; pass < 3; pass++) {
            const uint32_t Ab = sb + ((pass == 2) ? SM2_XL : SM2_XH) + aoff + (uint32_t)kc * 256;
            const uint32_t Bb = sb + ((pass == 1) ? SM2_WL : SM2_WH) + boff;
            #pragma unroll
            for (int ks = 0; ks < 8; ks++) {
                uint32_t a[4][4], b[2][4];
                #pragma unroll
                for (int mi = 0; mi < 4; mi++) ldsm4(a[mi], Ab + (mi * 16 * KPX + ks * 16) * 2);
                #pragma unroll
                for (int nb = 0; nb < 2; nb++) ldsm4(b[nb], Bb + (nb * 16 * KPW + ks * 16) * 2);
                #pragma unroll
                for (int mi = 0; mi < 4; mi++) {
                    mma_bf16(acc[mi][0], a[mi], &b[0][0]);
                    mma_bf16(acc[mi][1], a[mi], &b[0][2]);
                    mma_bf16(acc[mi][2], a[mi], &b[1][0]);
                    mma_bf16(acc[mi][3], a[mi], &b[1][2]);
                }
            }
        }
    }

    // fused epilogue: bias + relu + head dot -> per-row scalar
    const int g = lane >> 2, tg = lane & 3;
    float rs[4][2];
    #pragma unroll
    for (int mi = 0; mi < 4; mi++) { rs[mi][0] = 0.0f; rs[mi][1] = 0.0f; }
    #pragma unroll
    for (int mi = 0; mi < 4; mi++) {
        #pragma unroll
        for (int nj = 0; nj < 4; nj++) {
            int c0 = wn + nj * 8 + tg * 2;
            float w0 = wcs[c0], w1 = wcs[c0 + 1];
            float bb0 = b2s[c0], bb1 = b2s[c0 + 1];
            rs[mi][0] += fmaxf(acc[mi][nj][0] + bb0, 0.0f) * w0
                       + fmaxf(acc[mi][nj][1] + bb1, 0.0f) * w1;
            rs[mi][1] += fmaxf(acc[mi][nj][2] + bb0, 0.0f) * w0
                       + fmaxf(acc[mi][nj][3] + bb1, 0.0f) * w1;
        }
    }
    __syncthreads();
    #pragma unroll
    for (int mi = 0; mi < 4; mi++) {
        #pragma unroll
        for (int rb = 0; rb < 2; rb++) {
            float s = rs[mi][rb];
            s += __shfl_xor_sync(0xFFFFFFFFu, s, 1);
            s += __shfl_xor_sync(0xFFFFFFFFu, s, 2);
            if (tg == 0) atomicAdd(&stage[wm + mi * 16 + g + rb * 8], s);
        }
    }
    __syncthreads();
    if (tid < 128) g_part[(size_t)half * NB + row0 + tid] = stage[tid];
}

// ---------------- finalize ----------------
__global__ void k_final(float* __restrict__ out) {
    int i = blockIdx.x * blockDim.x + threadIdx.x;
    out[i] = g_part[i] + g_part[NB + i] + g_bc;
}

// ---------------- launch ----------------
extern "C" void kernel_launch(void* const* d_in, const int* in_sizes, int n_in,
                              void* d_out, int out_size) {
    const float* state  = (const float*)d_in[0];
    const float* action = (const float*)d_in[1];
    const float* alphas = (const float*)d_in[2];
    const float* W1     = (const float*)d_in[3];
    const float* b1     = (const float*)d_in[4];
    const float* W2     = (const float*)d_in[5];
    const float* b2     = (const float*)d_in[6];
    const float* Wh     = (const float*)d_in[7];
    const float* bh     = (const float*)d_in[8];
    float* out = (float*)d_out;

    cudaFuncSetAttribute(k_l1, cudaFuncAttributeMaxDynamicSharedMemorySize, SMEM_L1);
    cudaFuncSetAttribute(k_l2, cudaFuncAttributeMaxDynamicSharedMemorySize, SMEM_L2);

    k_prep<<<193, 256>>>(alphas, Wh, bh, W1, W2);
    k_prepx<<<2048, 256>>>(state, action);
    k_l1<<<1024, THREADS, SMEM_L1>>>(b1);
    k_l2<<<1024, THREADS, SMEM_L2>>>(b2);
    k_final<<<256, 256>>>(out);
}